// round 8
// baseline (speedup 1.0000x reference)
#include <cuda_runtime.h>
#include <cuda_bf16.h>
#include <stdint.h>

#define D       512
#define NB      512
#define NM      65536
#define BT      128
#define MT      128
#define KTB     64                 // k BYTES per stage per row (s8: 64 k-elems)
#define NSTG    (D / KTB)          // 8 stages (512 s8 bytes per row total)
#define ROWB    80                 // 64 B payload + 16 B pad (R6-proven conflict-free)
#define ABYTES  (128 * ROWB)       // 10240 per tile array
#define STGB    (2 * ABYTES)       // 20480 per stage (A+B)
#define NBUF    4
#define SMEM_DYN (NBUF * STGB)     // 81920
#define NTILES  (NM / MT)          // 512
#define NGRP    (NM / 8)           // 8192 8-row groups
#define DELTA   0.12f

// ---------------- device scratch (allocation-free rule) ----------------
__device__ int8_t g_mem_q[NM * D];          // normalized+quantized memory, s8 row-major
__device__ int8_t g_ctx_q[NB * D];          // quantized context, s8 row-major
__device__ float g_scale_m[NM];             // per-row quant scale (normalized units)
__device__ float g_scale_c[NB];             // per-row ctx quant scale
__device__ float g_inv_norm[NM];
__device__ float g_subbest[NB * NGRP];      // per (query, 8-row m-group) screen max
__device__ int   g_bestidx[NB];

// ---------------- helpers ----------------
__device__ __forceinline__ unsigned int f2mono(float f) {
    unsigned int b = __float_as_uint(f);
    return (b & 0x80000000u) ? ~b : (b | 0x80000000u);
}
__device__ __forceinline__ uint32_t s2u(const void* p) {
    return (uint32_t)__cvta_generic_to_shared(p);
}
__device__ __forceinline__ void cp16(uint32_t dst, const void* src) {
    asm volatile("cp.async.cg.shared.global [%0], [%1], 16;" :: "r"(dst), "l"(src));
}
__device__ __forceinline__ void ldm_x4(uint32_t& r0, uint32_t& r1, uint32_t& r2, uint32_t& r3, uint32_t a) {
    asm volatile("ldmatrix.sync.aligned.m8n8.x4.shared.b16 {%0,%1,%2,%3}, [%4];"
                 : "=r"(r0), "=r"(r1), "=r"(r2), "=r"(r3) : "r"(a));
}
// s8 k32 mma: fragment byte-layout identical to bf16 k16, so ldmatrix.b16 feeds it.
__device__ __forceinline__ void mma16832s8(int* c, const uint32_t* a, const uint32_t* b) {
    asm volatile("mma.sync.aligned.m16n8k32.row.col.s32.s8.s8.s32 "
                 "{%0,%1,%2,%3}, {%4,%5,%6,%7}, {%8,%9}, {%0,%1,%2,%3};"
                 : "+r"(c[0]), "+r"(c[1]), "+r"(c[2]), "+r"(c[3])
                 : "r"(a[0]), "r"(a[1]), "r"(a[2]), "r"(a[3]), "r"(b[0]), "r"(b[1]));
}

// ---------------- 1) convert fp32 -> s8 (memory rows normalized first) ----------------
__global__ __launch_bounds__(256) void convert_kernel(const float* __restrict__ src, int rows, int is_mem) {
    int row = blockIdx.x * 8 + (threadIdx.x >> 5);
    int lane = threadIdx.x & 31;
    if (row >= rows) return;
    const float4* rp = (const float4*)(src + (size_t)row * D);
    float4 v[4];
    float ssq = 0.f, mab = 0.f;
#pragma unroll
    for (int i = 0; i < 4; i++) {
        v[i] = rp[lane * 4 + i];
        ssq += v[i].x * v[i].x + v[i].y * v[i].y + v[i].z * v[i].z + v[i].w * v[i].w;
        mab = fmaxf(mab, fmaxf(fmaxf(fabsf(v[i].x), fabsf(v[i].y)),
                               fmaxf(fabsf(v[i].z), fabsf(v[i].w))));
    }
#pragma unroll
    for (int o = 16; o > 0; o >>= 1) {
        ssq += __shfl_xor_sync(0xffffffffu, ssq, o);
        mab = fmaxf(mab, __shfl_xor_sync(0xffffffffu, mab, o));
    }
    float invn = 1.0f;
    if (is_mem) {
        invn = rsqrtf(fmaxf(ssq, 1e-12f));
        if (lane == 0) g_inv_norm[row] = invn;
    }
    float maxq = fmaxf(mab * invn, 1e-20f);
    float scale = maxq * (1.0f / 127.0f);
    float iscale = 127.0f / maxq;
    if (lane == 0) {
        if (is_mem) g_scale_m[row] = scale; else g_scale_c[row] = scale;
    }
    // quantize this thread's 16 elems, pack into one uint4 (16 s8 bytes)
    const float* vs = (const float*)v;
    uint32_t wds[4];
#pragma unroll
    for (int g = 0; g < 4; g++) {
        uint32_t p = 0;
#pragma unroll
        for (int e = 0; e < 4; e++) {
            int q = __float2int_rn(vs[g * 4 + e] * invn * iscale);
            p |= ((uint32_t)(q & 0xFF)) << (e * 8);
        }
        wds[g] = p;
    }
    int8_t* dst = (is_mem ? g_mem_q : g_ctx_q) + (size_t)row * D + lane * 16;
    *(uint4*)dst = make_uint4(wds[0], wds[1], wds[2], wds[3]);
}

// ---------------- 2) s8 IMMA GEMM + per-(query, 8-m-group) max ----------------
// grid: (512 m-tiles [fastest], 4 b-tiles). 256 threads = 8 warps, warp = 64b x 32m.
// R6-proven pipeline: 64B/row stages, 4 buffers, prefetch depth 3, one sync/stage.
__global__ __launch_bounds__(256) void gemm_kernel() {
    extern __shared__ __align__(128) char dsm[];
    __shared__ float ssc[128];   // ctx quant scales for this b-tile
    __shared__ float ssm[128];   // mem quant scales for this m-tile

    const int tid = threadIdx.x, lane = tid & 31, w = tid >> 5;
    const int wb = w >> 2, wm = w & 3;
    const int mtile = blockIdx.x;
    const int b0 = blockIdx.y * BT;

    const int arow = tid >> 1;
    const int ac = (tid & 1) * 32;
    const char* asrc = (const char*)(g_ctx_q + (size_t)(b0 + arow) * D) + ac;
    const char* bsrc = (const char*)(g_mem_q + (size_t)(mtile * MT + arow) * D) + ac;
    const uint32_t smbase = s2u(dsm);
    const uint32_t adst = smbase + arow * ROWB + ac;

    int acc[4][4][4];
#pragma unroll
    for (int i = 0; i < 4; i++)
#pragma unroll
        for (int j = 0; j < 4; j++)
#pragma unroll
            for (int k = 0; k < 4; k++) acc[i][j][k] = 0;

    const uint32_t aoff = (uint32_t)((wb * 64 + (lane & 15)) * ROWB + (lane >> 4) * 16);
    const uint32_t boff = (uint32_t)(ABYTES + (wm * 32 + (lane >> 4) * 8 + (lane & 7)) * ROWB + ((lane >> 3) & 1) * 16);

    auto load_stage = [&](int s) {
        uint32_t off = (uint32_t)((s & (NBUF - 1)) * STGB);
        const char* a = asrc + s * 64;
        const char* b = bsrc + s * 64;
        cp16(adst + off, a);              cp16(adst + off + 16, a + 16);
        cp16(adst + off + ABYTES, b);     cp16(adst + off + ABYTES + 16, b + 16);
        asm volatile("cp.async.commit_group;" ::: "memory");
    };

    load_stage(0); load_stage(1); load_stage(2);
    if (tid < 128) ssc[tid] = g_scale_c[b0 + tid];
    else           ssm[tid - 128] = g_scale_m[mtile * MT + tid - 128];

    for (int s = 0; s < NSTG; s++) {
        if (s < NSTG - 2)       asm volatile("cp.async.wait_group 2;" ::: "memory");
        else if (s == NSTG - 2) asm volatile("cp.async.wait_group 1;" ::: "memory");
        else                    asm volatile("cp.async.wait_group 0;" ::: "memory");
        __syncthreads();
        if (s + 3 < NSTG) load_stage(s + 3);

        uint32_t sb = smbase + (uint32_t)((s & (NBUF - 1)) * STGB);
#pragma unroll
        for (int h = 0; h < 2; h++) {            // two k32 sub-steps per stage
            uint32_t afr[4][4], bfr[2][4];
#pragma unroll
            for (int i = 0; i < 4; i++)
                ldm_x4(afr[i][0], afr[i][1], afr[i][2], afr[i][3],
                       sb + aoff + (uint32_t)(i * 16 * ROWB + h * 32));
#pragma unroll
            for (int p = 0; p < 2; p++)
                ldm_x4(bfr[p][0], bfr[p][1], bfr[p][2], bfr[p][3],
                       sb + boff + (uint32_t)(p * 16 * ROWB + h * 32));
#pragma unroll
            for (int i = 0; i < 4; i++)
#pragma unroll
                for (int j = 0; j < 4; j++)
                    mma16832s8(acc[i][j], afr[i], &bfr[j >> 1][(j & 1) * 2]);
        }
    }

    // epilogue: rescale to float, per-(query row, 8-col group) max -> g_subbest
    float (*sg)[16] = (float(*)[16])dsm;
    const int c0 = 2 * (lane & 3);
#pragma unroll
    for (int i = 0; i < 4; i++)
#pragma unroll
        for (int j = 0; j < 4; j++) {
            int gcol = wm * 32 + j * 8;
            float sm0 = ssm[gcol + c0], sm1 = ssm[gcol + c0 + 1];
            float p0 = fmaxf((float)acc[i][j][0] * sm0, (float)acc[i][j][1] * sm1);
            float p1 = fmaxf((float)acc[i][j][2] * sm0, (float)acc[i][j][3] * sm1);
            p0 = fmaxf(p0, __shfl_xor_sync(0xffffffffu, p0, 1));
            p0 = fmaxf(p0, __shfl_xor_sync(0xffffffffu, p0, 2));
            p1 = fmaxf(p1, __shfl_xor_sync(0xffffffffu, p1, 1));
            p1 = fmaxf(p1, __shfl_xor_sync(0xffffffffu, p1, 2));
            if ((lane & 3) == 0) {
                int r = wb * 64 + i * 16 + (lane >> 2);
                sg[r][wm * 4 + j] = p0 * ssc[r];
                sg[r + 8][wm * 4 + j] = p1 * ssc[r + 8];
            }
        }
    __syncthreads();
    {
        int r = tid >> 1, half = tid & 1;
        float* dst = &g_subbest[(size_t)(b0 + r) * NGRP + mtile * 16 + half * 8];
        const float* src = &sg[r][half * 8];
        *(float4*)dst = *(const float4*)src;
        *(float4*)(dst + 4) = *(const float4*)(src + 4);
    }
}

// ---------------- 3) rescue: exact fp32 rescore of candidate 8-row groups ----------------
__global__ __launch_bounds__(256) void rescue_kernel(const float* __restrict__ ctx,
                                                     const float* __restrict__ mem) {
    __shared__ __align__(16) float sb[NGRP];     // 32 KB
    __shared__ __align__(16) float cs[D];
    __shared__ float sred[8];
    __shared__ float sthresh;
    __shared__ int clist[1024];
    __shared__ int ccount;
    __shared__ unsigned long long wkey[8];

    const int b = blockIdx.x, tid = threadIdx.x, wid = tid >> 5, lane = tid & 31;

    cs[tid] = ctx[(size_t)b * D + tid];
    cs[tid + 256] = ctx[(size_t)b * D + tid + 256];
    if (tid == 0) ccount = 0;

    float vmax = -3.4e38f;
    const float4* gsrc = (const float4*)&g_subbest[(size_t)b * NGRP];
#pragma unroll
    for (int i = 0; i < NGRP / 4 / 256; i++) {
        float4 v = gsrc[tid + i * 256];
        *(float4*)&sb[(tid + i * 256) * 4] = v;
        vmax = fmaxf(vmax, fmaxf(fmaxf(v.x, v.y), fmaxf(v.z, v.w)));
    }
#pragma unroll
    for (int o = 16; o > 0; o >>= 1) vmax = fmaxf(vmax, __shfl_xor_sync(0xffffffffu, vmax, o));
    if (lane == 0) sred[wid] = vmax;
    __syncthreads();
    if (tid == 0) {
        float m = sred[0];
#pragma unroll
        for (int i = 1; i < 8; i++) m = fmaxf(m, sred[i]);
        sthresh = m - DELTA;
    }
    __syncthreads();
    const float thresh = sthresh;

    for (int g = tid; g < NGRP; g += 256) {
        if (sb[g] >= thresh) {
            int pos = atomicAdd(&ccount, 1);
            if (pos < 1024) clist[pos] = g;
        }
    }
    __syncthreads();
    int nc = ccount; if (nc > 1024) nc = 1024;

    unsigned long long best = 0ull;
    for (int ci = wid; ci < nc; ci += 8) {
        int g = clist[ci];
#pragma unroll
        for (int r = 0; r < 8; r++) {
            int m = g * 8 + r;
            const float4* mr = (const float4*)(mem + (size_t)m * D);
            float s = 0.f;
#pragma unroll
            for (int i = 0; i < 4; i++) {
                float4 q = mr[lane + i * 32];
                float4 c = *(const float4*)&cs[(lane + i * 32) * 4];
                s = fmaf(q.x, c.x, s); s = fmaf(q.y, c.y, s);
                s = fmaf(q.z, c.z, s); s = fmaf(q.w, c.w, s);
            }
#pragma unroll
            for (int o = 16; o > 0; o >>= 1) s += __shfl_xor_sync(0xffffffffu, s, o);
            s *= g_inv_norm[m];
            unsigned long long key = ((unsigned long long)f2mono(s) << 32) |
                                     (unsigned long long)(0xFFFFFFFFu - (unsigned)m);
            if (key > best) best = key;
        }
    }
#pragma unroll
    for (int o = 16; o > 0; o >>= 1) {
        unsigned long long ok = __shfl_xor_sync(0xffffffffu, best, o);
        if (ok > best) best = ok;
    }
    if (lane == 0) wkey[wid] = best;
    __syncthreads();
    if (tid == 0) {
        unsigned long long k = wkey[0];
#pragma unroll
        for (int i = 1; i < 8; i++) if (wkey[i] > k) k = wkey[i];
        g_bestidx[b] = (int)(0xFFFFFFFFu - (unsigned)(k & 0xFFFFFFFFull));
    }
}

// ---------------- 4) gather ----------------
__global__ void gather_kernel(const float* __restrict__ mem, float* __restrict__ out) {
    int b = blockIdx.x;
    int idx = g_bestidx[b];
    const float4* src = (const float4*)(mem + (size_t)idx * D);
    float4* dst = (float4*)(out + (size_t)b * D);
    for (int i = threadIdx.x; i < D / 4; i += blockDim.x) dst[i] = src[i];
}

// ---------------- launch ----------------
extern "C" void kernel_launch(void* const* d_in, const int* in_sizes, int n_in,
                              void* d_out, int out_size)
{
    const float* ctx = (const float*)d_in[0];   // [512, 512] f32
    const float* mem = (const float*)d_in[1];   // [65536, 512] f32
    float* out = (float*)d_out;                 // [1, 512, 512] f32

    cudaFuncSetAttribute(gemm_kernel, cudaFuncAttributeMaxDynamicSharedMemorySize, SMEM_DYN);

    convert_kernel<<<NM / 8, 256>>>(mem, NM, 1);
    convert_kernel<<<NB / 8, 256>>>(ctx, NB, 0);
    gemm_kernel<<<dim3(NTILES, NB / BT), 256, SMEM_DYN>>>();
    rescue_kernel<<<NB, 256>>>(ctx, mem);
    gather_kernel<<<NB, 128>>>(mem, out);
}

// round 12
// speedup vs baseline: 1.5865x; 1.5865x over previous
#include <cuda_runtime.h>
#include <cuda_bf16.h>
#include <stdint.h>

#define D       512
#define NB      512
#define NM      65536
#define BT      128
#define MT      128
#define KT      32                 // k per pipeline stage (bf16 elems)
#define NSTG    (D / KT)           // 16
#define ROWB    80                 // padded smem row stride (bytes) -> conflict-free
#define ABYTES  (128 * ROWB)       // 10240 per tile array
#define STGB    (2 * ABYTES)       // 20480 per stage (A+B)
#define NBUF    4
#define SMEM_DYN (NBUF * STGB)     // 81920
#define NTILES  (NM / MT)          // 512
#define NGRP    (NM / 8)           // 8192 8-row groups
#define DELTA   0.09f

// ---------------- device scratch (allocation-free rule) ----------------
__device__ __nv_bfloat16 g_mem_b[NM * D];   // normalized memory, bf16 row-major
__device__ __nv_bfloat16 g_ctx_b[NB * D];   // context, bf16 row-major
__device__ float g_inv_norm[NM];
__device__ float g_subbest[NB * NGRP];      // per (query, 8-row m-group) screen max

// ---------------- helpers ----------------
__device__ __forceinline__ unsigned int f2mono(float f) {
    unsigned int b = __float_as_uint(f);
    return (b & 0x80000000u) ? ~b : (b | 0x80000000u);
}
__device__ __forceinline__ uint32_t s2u(const void* p) {
    return (uint32_t)__cvta_generic_to_shared(p);
}
__device__ __forceinline__ void cp16(uint32_t dst, const void* src) {
    asm volatile("cp.async.cg.shared.global [%0], [%1], 16;" :: "r"(dst), "l"(src));
}
__device__ __forceinline__ void ldm_x4(uint32_t& r0, uint32_t& r1, uint32_t& r2, uint32_t& r3, uint32_t a) {
    asm volatile("ldmatrix.sync.aligned.m8n8.x4.shared.b16 {%0,%1,%2,%3}, [%4];"
                 : "=r"(r0), "=r"(r1), "=r"(r2), "=r"(r3) : "r"(a));
}
__device__ __forceinline__ void mma16816(float* c, const uint32_t* a, const uint32_t* b) {
    asm volatile("mma.sync.aligned.m16n8k16.row.col.f32.bf16.bf16.f32 "
                 "{%0,%1,%2,%3}, {%4,%5,%6,%7}, {%8,%9}, {%0,%1,%2,%3};"
                 : "+f"(c[0]), "+f"(c[1]), "+f"(c[2]), "+f"(c[3])
                 : "r"(a[0]), "r"(a[1]), "r"(a[2]), "r"(a[3]), "r"(b[0]), "r"(b[1]));
}

// ---------------- 1) convert fp32 -> bf16 (memory rows normalized) ----------------
__global__ __launch_bounds__(256) void convert_kernel(const float* __restrict__ src, int rows, int is_mem) {
    int row = blockIdx.x * 8 + (threadIdx.x >> 5);
    int lane = threadIdx.x & 31;
    if (row >= rows) return;
    const float4* rp = (const float4*)(src + (size_t)row * D);
    float4 v[4];
    float ssq = 0.f;
#pragma unroll
    for (int i = 0; i < 4; i++) {
        v[i] = rp[lane * 4 + i];
        ssq += v[i].x * v[i].x + v[i].y * v[i].y + v[i].z * v[i].z + v[i].w * v[i].w;
    }
    float invn = 1.0f;
    if (is_mem) {
#pragma unroll
        for (int o = 16; o > 0; o >>= 1) ssq += __shfl_xor_sync(0xffffffffu, ssq, o);
        invn = rsqrtf(fmaxf(ssq, 1e-12f));
        if (lane == 0) g_inv_norm[row] = invn;
    }
    unsigned short h[16];
    const float* vs = (const float*)v;
#pragma unroll
    for (int i = 0; i < 16; i++)
        h[i] = __bfloat16_as_ushort(__float2bfloat16_rn(vs[i] * invn));
    __nv_bfloat16* dst = (is_mem ? g_mem_b : g_ctx_b) + (size_t)row * D + lane * 16;
#pragma unroll
    for (int g = 0; g < 2; g++) {
        uint4 w;
        w.x = ((uint32_t)h[g * 8 + 1] << 16) | h[g * 8 + 0];
        w.y = ((uint32_t)h[g * 8 + 3] << 16) | h[g * 8 + 2];
        w.z = ((uint32_t)h[g * 8 + 5] << 16) | h[g * 8 + 4];
        w.w = ((uint32_t)h[g * 8 + 7] << 16) | h[g * 8 + 6];
        *(uint4*)(dst + g * 8) = w;
    }
}

// ---------------- 2) HMMA GEMM + per-(query, 8-m-group) max  (R6-proven) ----------------
// grid: (512 m-tiles [fastest], 4 b-tiles). 256 threads = 8 warps, warp = 64b x 32m.
// 4-stage cp.async pipeline, prefetch depth 3, one __syncthreads per stage.
__global__ __launch_bounds__(256) void gemm_kernel() {
    extern __shared__ __align__(128) char dsm[];

    const int tid = threadIdx.x, lane = tid & 31, w = tid >> 5;
    const int wb = w >> 2, wm = w & 3;           // warp b-half, warp m-quarter
    const int mtile = blockIdx.x;
    const int b0 = blockIdx.y * BT;

    const int arow = tid >> 1;
    const int ac = (tid & 1) * 32;
    const char* asrc = (const char*)(g_ctx_b + (size_t)(b0 + arow) * D) + ac;
    const char* bsrc = (const char*)(g_mem_b + (size_t)(mtile * MT + arow) * D) + ac;
    const uint32_t smbase = s2u(dsm);
    const uint32_t adst = smbase + arow * ROWB + ac;

    float acc[4][4][4];
#pragma unroll
    for (int i = 0; i < 4; i++)
#pragma unroll
        for (int j = 0; j < 4; j++)
#pragma unroll
            for (int k = 0; k < 4; k++) acc[i][j][k] = 0.f;

    const uint32_t aoff = (uint32_t)((wb * 64 + (lane & 15)) * ROWB + (lane >> 4) * 16);
    const uint32_t boff = (uint32_t)(ABYTES + (wm * 32 + (lane >> 4) * 8 + (lane & 7)) * ROWB + ((lane >> 3) & 1) * 16);

    auto load_stage = [&](int s) {
        uint32_t off = (uint32_t)((s & (NBUF - 1)) * STGB);
        const char* a = asrc + s * 64;
        const char* b = bsrc + s * 64;
        cp16(adst + off, a);              cp16(adst + off + 16, a + 16);
        cp16(adst + off + ABYTES, b);     cp16(adst + off + ABYTES + 16, b + 16);
        asm volatile("cp.async.commit_group;" ::: "memory");
    };

    load_stage(0); load_stage(1); load_stage(2);

    for (int s = 0; s < NSTG; s++) {
        if (s < NSTG - 2)       asm volatile("cp.async.wait_group 2;" ::: "memory");
        else if (s == NSTG - 2) asm volatile("cp.async.wait_group 1;" ::: "memory");
        else                    asm volatile("cp.async.wait_group 0;" ::: "memory");
        __syncthreads();
        if (s + 3 < NSTG) load_stage(s + 3);

        uint32_t sb = smbase + (uint32_t)((s & (NBUF - 1)) * STGB);
#pragma unroll
        for (int h = 0; h < 2; h++) {
            uint32_t afr[4][4], bfr[2][4];
#pragma unroll
            for (int i = 0; i < 4; i++)
                ldm_x4(afr[i][0], afr[i][1], afr[i][2], afr[i][3],
                       sb + aoff + (uint32_t)(i * 16 * ROWB + h * 32));
#pragma unroll
            for (int p = 0; p < 2; p++)
                ldm_x4(bfr[p][0], bfr[p][1], bfr[p][2], bfr[p][3],
                       sb + boff + (uint32_t)(p * 16 * ROWB + h * 32));
#pragma unroll
            for (int i = 0; i < 4; i++)
#pragma unroll
                for (int j = 0; j < 4; j++)
                    mma16816(acc[i][j], afr[i], &bfr[j >> 1][(j & 1) * 2]);
        }
    }

    // epilogue: per-(query row, 8-col mma group) max -> g_subbest
    float (*sg)[16] = (float(*)[16])dsm;
#pragma unroll
    for (int i = 0; i < 4; i++)
#pragma unroll
        for (int j = 0; j < 4; j++) {
            float p0 = fmaxf(acc[i][j][0], acc[i][j][1]);
            float p1 = fmaxf(acc[i][j][2], acc[i][j][3]);
            p0 = fmaxf(p0, __shfl_xor_sync(0xffffffffu, p0, 1));
            p0 = fmaxf(p0, __shfl_xor_sync(0xffffffffu, p0, 2));
            p1 = fmaxf(p1, __shfl_xor_sync(0xffffffffu, p1, 1));
            p1 = fmaxf(p1, __shfl_xor_sync(0xffffffffu, p1, 2));
            if ((lane & 3) == 0) {
                int r = wb * 64 + i * 16 + (lane >> 2);
                sg[r][wm * 4 + j] = p0;
                sg[r + 8][wm * 4 + j] = p1;
            }
        }
    __syncthreads();
    {   // thread t writes row t>>1, half t&1 (8 floats, 32B contiguous)
        int r = tid >> 1, half = tid & 1;
        float* dst = &g_subbest[(size_t)(b0 + r) * NGRP + mtile * 16 + half * 8];
        const float* src = &sg[r][half * 8];
        *(float4*)dst = *(const float4*)src;
        *(float4*)(dst + 4) = *(const float4*)(src + 4);
    }
}

// ---------------- 3) rescue + gather fused ----------------
// Per query block: exact fp32 rescore of candidate 8-row groups, then copy
// the winning memory row straight to out (winner is block-local).
__global__ __launch_bounds__(256) void rescue_kernel(const float* __restrict__ ctx,
                                                     const float* __restrict__ mem,
                                                     float* __restrict__ out) {
    __shared__ __align__(16) float sb[NGRP];     // 32 KB
    __shared__ __align__(16) float cs[D];
    __shared__ float sred[8];
    __shared__ float sthresh;
    __shared__ int clist[1024];
    __shared__ int ccount;
    __shared__ unsigned long long wkey[8];
    __shared__ int sbest;

    const int b = blockIdx.x, tid = threadIdx.x, wid = tid >> 5, lane = tid & 31;

    cs[tid] = ctx[(size_t)b * D + tid];
    cs[tid + 256] = ctx[(size_t)b * D + tid + 256];
    if (tid == 0) ccount = 0;

    float vmax = -3.4e38f;
    const float4* gsrc = (const float4*)&g_subbest[(size_t)b * NGRP];
#pragma unroll
    for (int i = 0; i < NGRP / 4 / 256; i++) {   // 8 iters
        float4 v = gsrc[tid + i * 256];
        *(float4*)&sb[(tid + i * 256) * 4] = v;
        vmax = fmaxf(vmax, fmaxf(fmaxf(v.x, v.y), fmaxf(v.z, v.w)));
    }
#pragma unroll
    for (int o = 16; o > 0; o >>= 1) vmax = fmaxf(vmax, __shfl_xor_sync(0xffffffffu, vmax, o));
    if (lane == 0) sred[wid] = vmax;
    __syncthreads();
    if (tid == 0) {
        float m = sred[0];
#pragma unroll
        for (int i = 1; i < 8; i++) m = fmaxf(m, sred[i]);
        sthresh = m - DELTA;
    }
    __syncthreads();
    const float thresh = sthresh;

    for (int g = tid; g < NGRP; g += 256) {
        if (sb[g] >= thresh) {
            int pos = atomicAdd(&ccount, 1);
            if (pos < 1024) clist[pos] = g;
        }
    }
    __syncthreads();
    int nc = ccount; if (nc > 1024) nc = 1024;

    unsigned long long best = 0ull;
    for (int ci = wid; ci < nc; ci += 8) {
        int g = clist[ci];
#pragma unroll
        for (int r = 0; r < 8; r++) {
            int m = g * 8 + r;
            const float4* mr = (const float4*)(mem + (size_t)m * D);
            float s = 0.f;
#pragma unroll
            for (int i = 0; i < 4; i++) {
                float4 q = mr[lane + i * 32];
                float4 c = *(const float4*)&cs[(lane + i * 32) * 4];
                s = fmaf(q.x, c.x, s); s = fmaf(q.y, c.y, s);
                s = fmaf(q.z, c.z, s); s = fmaf(q.w, c.w, s);
            }
#pragma unroll
            for (int o = 16; o > 0; o >>= 1) s += __shfl_xor_sync(0xffffffffu, s, o);
            s *= g_inv_norm[m];
            unsigned long long key = ((unsigned long long)f2mono(s) << 32) |
                                     (unsigned long long)(0xFFFFFFFFu - (unsigned)m);
            if (key > best) best = key;
        }
    }
#pragma unroll
    for (int o = 16; o > 0; o >>= 1) {
        unsigned long long ok = __shfl_xor_sync(0xffffffffu, best, o);
        if (ok > best) best = ok;
    }
    if (lane == 0) wkey[wid] = best;
    __syncthreads();
    if (tid == 0) {
        unsigned long long k = wkey[0];
#pragma unroll
        for (int i = 1; i < 8; i++) if (wkey[i] > k) k = wkey[i];
        sbest = (int)(0xFFFFFFFFu - (unsigned)(k & 0xFFFFFFFFull));
    }
    __syncthreads();

    // fused gather: out[0, b, :] = memory[sbest, :]
    const int idx = sbest;
    const float4* src = (const float4*)(mem + (size_t)idx * D);
    float4* dst = (float4*)(out + (size_t)b * D);
    if (tid < D / 4) dst[tid] = src[tid];
}

// ---------------- launch ----------------
extern "C" void kernel_launch(void* const* d_in, const int* in_sizes, int n_in,
                              void* d_out, int out_size)
{
    const float* ctx = (const float*)d_in[0];   // [512, 512] f32
    const float* mem = (const float*)d_in[1];   // [65536, 512] f32
    float* out = (float*)d_out;                 // [1, 512, 512] f32

    cudaFuncSetAttribute(gemm_kernel, cudaFuncAttributeMaxDynamicSharedMemorySize, SMEM_DYN);

    convert_kernel<<<NM / 8, 256>>>(mem, NM, 1);
    convert_kernel<<<NB / 8, 256>>>(ctx, NB, 0);
    gemm_kernel<<<dim3(NTILES, NB / BT), 256, SMEM_DYN>>>();
    rescue_kernel<<<NB, 256>>>(ctx, mem, out);
}